// round 16
// baseline (speedup 1.0000x reference)
#include <cuda_runtime.h>
#include <cuda.h>
#include <cuda_fp16.h>
#include <cstdint>

#define T_TOK 8192
#define DIMK 7168
#define ED 1024
#define NCMP 2048
#define HEAD_DIM_ 512
#define ROPE_DIM_ 64
#define NOPE_DIM_ 448
#define NUM_SLOTS_ 65536
#define EPS_ 1e-6f

// persistent cg2 GEMM: 64 clusters x 2 jobs; N=256/pair; split driver threads
#define BM 128
#define BN 256
#define BNH 128
#define BKE 64               // 64 fp16 = 128 B rows
#define NK (DIMK / BKE)                       // 112
#define NJOB 2
#define GTOT (NJOB * NK)                      // 224
#define NSTAGE 4
#define A_OFF 0
#define BP_OFF (BM * BKE * 2)                 // 16384
#define BG_OFF (BP_OFF + BNH * BKE * 2)       // 32768
#define STAGE_BYTES (BG_OFF + BNH * BKE * 2)  // 49152
#define TX_TOTAL (2 * STAGE_BYTES)            // 98304
#define ASUM_OFF (NSTAGE * STAGE_BYTES)       // 196608
#define SMEM_DYN (NSTAGE * STAGE_BYTES + 2048) // 198656

// idesc cg2 kind::f16: dtype=F32(1), N=256, M=256
#define IDESC ((1u << 4) | ((BN / 8) << 17) | ((256 / 16) << 24))

#if defined(__CUDA_ARCH_FEAT_SM103_ALL) || defined(__CUDA_ARCH_FEAT_SM100_ALL) || \
    (defined(__CUDA_ARCH_SPECIFIC__) && (__CUDA_ARCH_SPECIFIC__ >= 1000))
#define HAS_TCGEN05 1
#else
#define HAS_TCGEN05 0
#endif

__device__ float  g_kv_pre[(size_t)NCMP * ED];
__device__ __half g_x_h[(size_t)T_TOK * DIMK];
__device__ __half g_wkv_h[(size_t)ED * DIMK];
__device__ __half g_wgate_h[(size_t)ED * DIMK];
__device__ int    g_xflag[16];   // job-1 m-tile conversion counters (8 = ready)

// ---------------------------------------------------------------------------
__device__ __forceinline__ uint32_t smem_u32(const void* p) {
    return (uint32_t)__cvta_generic_to_shared(p);
}
__device__ __forceinline__ uint32_t ctarank() {
    uint32_t r; asm("mov.u32 %0, %%cluster_ctarank;" : "=r"(r)); return r;
}
__device__ __forceinline__ uint64_t make_desc(uint32_t addr) {
    const uint64_t base = (2ull << 61) | (1ull << 46) | (64ull << 32) | (1ull << 16);
    return base | ((uint64_t)(addr >> 4) & 0x3FFF);
}
__device__ __forceinline__ void mbar_init(uint32_t mbar, uint32_t count) {
    asm volatile("mbarrier.init.shared.b64 [%0], %1;" :: "r"(mbar), "r"(count) : "memory");
}
__device__ __forceinline__ void mbar_expect_tx(uint32_t mbar, uint32_t bytes) {
    asm volatile("mbarrier.arrive.expect_tx.shared.b64 _, [%0], %1;"
                 :: "r"(mbar), "r"(bytes) : "memory");
}
__device__ __forceinline__ void mbar_arrive(uint32_t mbar) {
    asm volatile("mbarrier.arrive.shared.b64 _, [%0];" :: "r"(mbar) : "memory");
}
__device__ __forceinline__ void mbar_arrive_cluster(uint32_t local_mbar, uint32_t target_rank) {
    asm volatile(
        "{\n\t.reg .b32 ra;\n\t"
        "mapa.shared::cluster.u32 ra, %0, %1;\n\t"
        "mbarrier.arrive.release.cluster.shared::cluster.b64 _, [ra];\n\t}"
        :: "r"(local_mbar), "r"(target_rank) : "memory");
}
__device__ __forceinline__ void mbar_wait(uint32_t mbar, uint32_t parity) {
    asm volatile(
        "{\n\t.reg .pred P1;\n\t"
        "WAIT_%=:\n\t"
        "mbarrier.try_wait.parity.acquire.cta.shared::cta.b64 P1, [%0], %1, 0x989680;\n\t"
        "@P1 bra DONE_%=;\n\t"
        "bra WAIT_%=;\n\t"
        "DONE_%=:\n\t}"
        :: "r"(mbar), "r"(parity) : "memory");
}
__device__ __forceinline__ void mbar_inval(uint32_t mbar) {
    asm volatile("mbarrier.inval.shared.b64 [%0];" :: "r"(mbar) : "memory");
}
__device__ __forceinline__ int ld_acquire(const int* p) {
    int v;
    asm volatile("ld.acquire.gpu.global.b32 %0, [%1];" : "=r"(v) : "l"(p) : "memory");
    return v;
}
#define CLUSTER_SYNC() do { \
    asm volatile("barrier.cluster.arrive.aligned;" ::: "memory"); \
    asm volatile("barrier.cluster.wait.aligned;" ::: "memory"); \
} while (0)

#if HAS_TCGEN05
__device__ __forceinline__ void tma2d_cg2(uint32_t dst, const CUtensorMap* map,
                                          int cx, int cy, uint32_t mbar) {
    asm volatile(
        "{\n\t.reg .b32 lb;\n\t"
        "and.b32 lb, %4, 0xFEFFFFFF;\n\t"
        "cp.async.bulk.tensor.2d.cta_group::2.shared::cluster.global.tile."
        "mbarrier::complete_tx::bytes [%0], [%1, {%2, %3}], [lb];\n\t}"
        :: "r"(dst), "l"(map), "r"(cx), "r"(cy), "r"(mbar) : "memory");
}
__device__ __forceinline__ void mma_f16_cg2(uint32_t d_tmem, uint64_t a_desc,
                                            uint64_t b_desc, uint32_t idesc, uint32_t en) {
    asm volatile(
        "{\n\t.reg .pred p;\n\t"
        "setp.ne.u32 p, %5, 0;\n\t"
        "tcgen05.mma.cta_group::2.kind::f16 [%0], %1, %2, %3, "
        "{%4, %4, %4, %4, %4, %4, %4, %4}, p;\n\t}"
        :: "r"(d_tmem), "l"(a_desc), "l"(b_desc), "r"(idesc), "r"(0u), "r"(en)
        : "memory");
}
__device__ __forceinline__ void tcg_commit_mc(uint32_t mbar, uint16_t mask) {
    asm volatile(
        "tcgen05.commit.cta_group::2.mbarrier::arrive::one.shared::cluster."
        "multicast::cluster.b64 [%0], %1;"
        :: "r"(mbar), "h"(mask) : "memory");
}
#define TCG_ALLOC_CG2(sm_addr, n) \
    asm volatile("tcgen05.alloc.cta_group::2.sync.aligned.shared::cta.b32 [%0], %1;" \
                 :: "r"(sm_addr), "r"(n) : "memory")
#define TCG_DEALLOC_CG2(tmem, n) \
    asm volatile("tcgen05.dealloc.cta_group::2.sync.aligned.b32 %0, %1;" :: "r"(tmem), "r"(n))
#define TCG_RELINQ_CG2() \
    asm volatile("tcgen05.relinquish_alloc_permit.cta_group::2.sync.aligned;")
#define TCG_FENCE_AFTER()  asm volatile("tcgen05.fence::after_thread_sync;" ::: "memory")
#define TCG_FENCE_BEFORE() asm volatile("tcgen05.fence::before_thread_sync;" ::: "memory")
#define TCG_WAIT_LD()      asm volatile("tcgen05.wait::ld.sync.aligned;" ::: "memory")

#define TCG_LD_X32(r, addr) \
    asm volatile( \
        "tcgen05.ld.sync.aligned.32x32b.x32.b32 " \
        "{%0, %1, %2, %3, %4, %5, %6, %7, " \
        " %8, %9, %10, %11, %12, %13, %14, %15, " \
        " %16, %17, %18, %19, %20, %21, %22, %23, " \
        " %24, %25, %26, %27, %28, %29, %30, %31}, [%32];" \
        : "=r"((r)[0]),  "=r"((r)[1]),  "=r"((r)[2]),  "=r"((r)[3]), \
          "=r"((r)[4]),  "=r"((r)[5]),  "=r"((r)[6]),  "=r"((r)[7]), \
          "=r"((r)[8]),  "=r"((r)[9]),  "=r"((r)[10]), "=r"((r)[11]), \
          "=r"((r)[12]), "=r"((r)[13]), "=r"((r)[14]), "=r"((r)[15]), \
          "=r"((r)[16]), "=r"((r)[17]), "=r"((r)[18]), "=r"((r)[19]), \
          "=r"((r)[20]), "=r"((r)[21]), "=r"((r)[22]), "=r"((r)[23]), \
          "=r"((r)[24]), "=r"((r)[25]), "=r"((r)[26]), "=r"((r)[27]), \
          "=r"((r)[28]), "=r"((r)[29]), "=r"((r)[30]), "=r"((r)[31]) \
        : "r"(addr))
#endif  // HAS_TCGEN05

// ---------------------------------------------------------------------------
// fp32 -> fp16 conversion; first kernel also zeroes the x-conversion flags
// ---------------------------------------------------------------------------
__global__ __launch_bounds__(256) void cvt_f16_flags_kernel(
    const float* __restrict__ src, __half* __restrict__ dst)
{
    if (blockIdx.x == 0 && threadIdx.x < 16) g_xflag[threadIdx.x] = 0;
    const size_t i = (size_t)blockIdx.x * 256 + threadIdx.x;
    float4 v = reinterpret_cast<const float4*>(src)[i];
    __half2 lo = __floats2half2_rn(v.x, v.y);
    __half2 hi = __floats2half2_rn(v.z, v.w);
    reinterpret_cast<__half2*>(dst)[2 * i]     = lo;
    reinterpret_cast<__half2*>(dst)[2 * i + 1] = hi;
}

__global__ __launch_bounds__(256) void cvt_f16_kernel(
    const float* __restrict__ src, __half* __restrict__ dst)
{
    const size_t i = (size_t)blockIdx.x * 256 + threadIdx.x;
    float4 v = reinterpret_cast<const float4*>(src)[i];
    __half2 lo = __floats2half2_rn(v.x, v.y);
    __half2 hi = __floats2half2_rn(v.z, v.w);
    reinterpret_cast<__half2*>(dst)[2 * i]     = lo;
    reinterpret_cast<__half2*>(dst)[2 * i + 1] = hi;
}

// ---------------------------------------------------------------------------
// persistent cg2 fp16 dual-GEMM: 64 clusters x 2 jobs, split-driver,
// spare warps 6-7 convert job-1 x slabs in-flight (flag-gated refill)
// job mapping: n_tile = cl & 3 (fixed), m_pair_tile = (cl>>2) + 16*j
// ---------------------------------------------------------------------------
__global__ __launch_bounds__(256, 1) __cluster_dims__(2, 1, 1) void gemm_tc_kernel(
    const __grid_constant__ CUtensorMap tmx,
    const __grid_constant__ CUtensorMap tmk,
    const __grid_constant__ CUtensorMap tmg,
    const float* __restrict__ x,
    const float* __restrict__ ape)
{
    extern __shared__ float dsm[];
    const int tid  = threadIdx.x;
    const uint32_t rank = ctarank();
    const int cl = blockIdx.x >> 1;            // 0..63
    const int e0 = (cl & 3) * BN;              // N-tile base, fixed

#if HAS_TCGEN05
    const int eb = e0 + (int)rank * BNH;
    __shared__ uint32_t s_tmem;
    __shared__ __align__(8) uint64_t s_mbar[10]; // full[4] empty[4] done free

    const int warp = tid >> 5;
    const int lane = tid & 31;
    const bool leader = (rank == 0);

    const uint32_t sb_raw = smem_u32(dsm);
    const uint32_t base   = (sb_raw + 1023u) & ~1023u;
    float* s_asum = (float*)((char*)dsm + (base - sb_raw) + ASUM_OFF);  // 256 floats
    uint32_t mb_full[NSTAGE], mb_empty[NSTAGE];
#pragma unroll
    for (int s = 0; s < NSTAGE; s++) {
        mb_full[s]  = smem_u32(&s_mbar[s]);
        mb_empty[s] = smem_u32(&s_mbar[NSTAGE + s]);
    }
    const uint32_t mb_done = smem_u32(&s_mbar[8]);
    const uint32_t mb_free = smem_u32(&s_mbar[9]);

    if (warp == 0) TCG_ALLOC_CG2(smem_u32(&s_tmem), 512);
    {
        const int e = e0 + tid;
        s_asum[tid] = ape[e] + ape[ED + e] + ape[2 * ED + e] + ape[3 * ED + e];
    }
    if (tid == 0) {
#pragma unroll
        for (int s = 0; s < NSTAGE; s++) {
            mbar_init(mb_full[s], 1);
            mbar_init(mb_empty[s], 1);
        }
        mbar_init(mb_done, 1);
        mbar_init(mb_free, 8);          // 4 warps x 2 CTAs
        if (leader) {
#pragma unroll
            for (int s = 0; s < NSTAGE; s++) mbar_expect_tx(mb_full[s], TX_TOTAL);
        }
    }
    __syncthreads();
    CLUSTER_SYNC();
    const uint32_t tmem = s_tmem;   // proj @ [0,256), gate @ [256,512)

    if (tid == 160) {
        // ---- refill thread (both CTAs): prefetch + steady-state refills
#pragma unroll
        for (int s = 0; s < NSTAGE; s++) {
            const int ty = (cl >> 2) * 256 + (int)rank * BM;   // job 0
            const uint32_t sa = base + s * STAGE_BYTES;
            tma2d_cg2(sa + A_OFF,  &tmx, s * BKE, ty, mb_full[s]);
            tma2d_cg2(sa + BP_OFF, &tmk, s * BKE, eb, mb_full[s]);
            tma2d_cg2(sa + BG_OFF, &tmg, s * BKE, eb, mb_full[s]);
        }
        int phe[NSTAGE] = {0, 0, 0, 0};
#pragma unroll 1
        for (int t = NSTAGE; t < GTOT; t++) {
            if (t == NK) {     // first job-1 A tile: wait for its x slab
                const int* fp = &g_xflag[cl >> 2];
                while (ld_acquire(fp) != 8) { }
            }
            const int s = t & (NSTAGE - 1);
            mbar_wait(mb_empty[s], phe[s]); phe[s] ^= 1;
            const int jt = t / NK;
            const int ck = t - jt * NK;
            const int ty = ((cl >> 2) + 16 * jt) * 256 + (int)rank * BM;
            const uint32_t sa = base + s * STAGE_BYTES;
            tma2d_cg2(sa + A_OFF,  &tmx, ck * BKE, ty, mb_full[s]);
            tma2d_cg2(sa + BP_OFF, &tmk, ck * BKE, eb, mb_full[s]);
            tma2d_cg2(sa + BG_OFF, &tmg, ck * BKE, eb, mb_full[s]);
        }
    } else if (tid == 128 && leader) {
        // ---- MMA driver: minimal per-iteration critical path
        int phf[NSTAGE] = {0, 0, 0, 0};
#pragma unroll 1
        for (int g = 0; g < GTOT; g++) {
            if (g == NK) mbar_wait(mb_free, 0);   // job 1 overwrites TMEM
            const int s = g & (NSTAGE - 1);
            mbar_wait(mb_full[s], phf[s]); phf[s] ^= 1;
            const uint32_t sa = base + s * STAGE_BYTES;
            const uint64_t ad  = make_desc(sa + A_OFF);
            const uint64_t bpd = make_desc(sa + BP_OFF);
            const uint64_t bgd = make_desc(sa + BG_OFF);
            const uint32_t en0 = (g != 0) && (g != NK);
#pragma unroll
            for (int ks = 0; ks < 4; ks++) {
                const uint32_t en = en0 | (uint32_t)(ks > 0);
                mma_f16_cg2(tmem,      ad + 2 * ks, bpd + 2 * ks, IDESC, en);
                mma_f16_cg2(tmem + BN, ad + 2 * ks, bgd + 2 * ks, IDESC, en);
            }
            if (g + NSTAGE < GTOT) mbar_expect_tx(mb_full[s], TX_TOTAL);
            tcg_commit_mc(mb_empty[s], 0x3);
            if (g == NK - 1 || g == GTOT - 1) tcg_commit_mc(mb_done, 0x3);
        }
    } else if (warp < 4) {
        // ---- epilogue consumers
#pragma unroll 1
        for (int j = 0; j < NJOB; j++) {
            mbar_wait(mb_done, j);
            TCG_FENCE_AFTER();
            const int t0j = ((cl >> 2) + 16 * j) * 256 + (int)rank * BM;
            const int n0  = t0j >> 2;
#pragma unroll 1
            for (int cb = 0; cb < 8; cb++) {
                uint32_t pr[32], gr[32];
                TCG_LD_X32(pr, tmem + cb * 32);
                TCG_LD_X32(gr, tmem + BN + cb * 32);
                TCG_WAIT_LD();
                float v[32];
#pragma unroll
                for (int i = 0; i < 32; i++) {
                    float p = __uint_as_float(pr[i]);
                    float gg = __uint_as_float(gr[i]);
                    v[i] = p / (1.f + __expf(-gg));
                }
#pragma unroll
                for (int i = 0; i < 32; i++) {
                    v[i] += __shfl_xor_sync(0xffffffffu, v[i], 1);
                    v[i] += __shfl_xor_sync(0xffffffffu, v[i], 2);
                }
                if ((lane & 3) == 0) {
                    const int row = warp * 8 + (lane >> 2);
                    float* dst = g_kv_pre + (size_t)(n0 + row) * ED + e0 + cb * 32;
                    const float* as = s_asum + cb * 32;
#pragma unroll
                    for (int q = 0; q < 8; q++) {
                        float4 o;
                        o.x = 0.25f * (v[4 * q]     + as[4 * q]);
                        o.y = 0.25f * (v[4 * q + 1] + as[4 * q + 1]);
                        o.z = 0.25f * (v[4 * q + 2] + as[4 * q + 2]);
                        o.w = 0.25f * (v[4 * q + 3] + as[4 * q + 3]);
                        reinterpret_cast<float4*>(dst)[q] = o;
                    }
                }
            }
            TCG_FENCE_BEFORE();
            if (lane == 0) {
                if (leader) mbar_arrive(mb_free);
                else        mbar_arrive_cluster(mb_free, 0);
            }
        }
    } else if (warp >= 6) {
        // ---- x converters (warps 6-7, 64 threads): convert this cluster's
        // quarter of its job-1 A slab: rows (16+m)*256 + q*64 + rank*32 .. +32
        const int m = cl >> 2;
        const int q = cl & 3;
        const size_t row0 = (size_t)(16 + m) * 256 + (size_t)q * 64 + (size_t)rank * 32;
        const size_t base_e = row0 * DIMK;            // element offset (16B aligned)
        const int ctid = tid - 192;                   // 0..63
        const float4* src4 = reinterpret_cast<const float4*>(x + base_e);
        uint2* dst2 = reinterpret_cast<uint2*>(g_x_h + base_e);
        const int nf4 = 32 * DIMK / 4;                // 57344
#pragma unroll 4
        for (int i = ctid; i < nf4; i += 64) {
            float4 v = src4[i];
            __half2 lo = __floats2half2_rn(v.x, v.y);
            __half2 hi = __floats2half2_rn(v.z, v.w);
            uint2 o;
            o.x = *reinterpret_cast<uint32_t*>(&lo);
            o.y = *reinterpret_cast<uint32_t*>(&hi);
            dst2[i] = o;
        }
        asm volatile("bar.sync 14, 64;" ::: "memory");   // warps 6-7 of this CTA
        __threadfence();
        if (ctid == 0) atomicAdd(&g_xflag[m], 1);
    }
    __syncthreads();
    CLUSTER_SYNC();   // peer free-arrivals land before inval
    if (tid == 0) {
#pragma unroll
        for (int s = 0; s < NSTAGE; s++) { mbar_inval(mb_full[s]); mbar_inval(mb_empty[s]); }
        mbar_inval(mb_done);
        mbar_inval(mb_free);
    }
    __syncthreads();
    if (warp == 0) { TCG_RELINQ_CG2(); TCG_DEALLOC_CG2(tmem, 512); }
    CLUSTER_SYNC();

#else  // ---- generic-PTX fallback (correct, never executed on GB300) ----
    for (int j = 0; j < NJOB; j++) {
        const int t0j = ((cl >> 2) + 16 * j) * 256 + (int)rank * BM;
        const int n0 = t0j >> 2;
        for (int idx = tid; idx < 32 * BN; idx += 256) {
            int row = idx / BN, col = idx % BN;
            int e = e0 + col;
            float acc = 0.f;
            for (int r = 0; r < 4; r++) {
                const float* xr = x + (size_t)(t0j + row * 4 + r) * DIMK;
                const __half* wk = g_wkv_h + (size_t)e * DIMK;
                const __half* wg = g_wgate_h + (size_t)e * DIMK;
                float p = 0.f, g = 0.f;
                for (int k = 0; k < DIMK; k++) {
                    float xv = __half2float(__float2half(xr[k]));
                    p += xv * __half2float(wk[k]);
                    g += xv * __half2float(wg[k]);
                }
                acc += p / (1.f + __expf(-g));
            }
            float asum = ape[e] + ape[ED + e] + ape[2 * ED + e] + ape[3 * ED + e];
            g_kv_pre[(size_t)(n0 + row) * ED + e] = 0.25f * (acc + asum);
        }
    }
    (void)dsm;
#endif
}

// ---------------------------------------------------------------------------
// RMS-norm (per 512) + partial RoPE + scatter
// ---------------------------------------------------------------------------
__global__ __launch_bounds__(256) void norm_rope_scatter_kernel(
    const float* __restrict__ norm_weight, const float* __restrict__ rope_cos,
    const float* __restrict__ rope_sin, const int* __restrict__ slot_mapping,
    float* __restrict__ out)
{
    __shared__ float vals[ED];
    __shared__ float wsum[8];
    const int n = blockIdx.x;
    const int tid = threadIdx.x;

    float4 v = reinterpret_cast<const float4*>(g_kv_pre)[(size_t)n * 256 + tid];
    float ssq = v.x * v.x + v.y * v.y + v.z * v.z + v.w * v.w;
#pragma unroll
    for (int off = 16; off > 0; off >>= 1)
        ssq += __shfl_xor_sync(0xffffffffu, ssq, off);
    if ((tid & 31) == 0) wsum[tid >> 5] = ssq;
    __syncthreads();

    const int c = tid >> 7;
    float tot = wsum[c * 4] + wsum[c * 4 + 1] + wsum[c * 4 + 2] + wsum[c * 4 + 3];
    float scale = rsqrtf(tot * (1.0f / HEAD_DIM_) + EPS_);
    float4 nw = reinterpret_cast<const float4*>(norm_weight)[tid & 127];
    v.x *= scale * nw.x; v.y *= scale * nw.y; v.z *= scale * nw.z; v.w *= scale * nw.w;
    reinterpret_cast<float4*>(vals)[tid] = v;
    __syncthreads();

    const int din = tid & 127;
    if (din >= 112) {
        int rd = (din - 112) * 4;
        const float* cb = rope_cos + (size_t)n * ROPE_DIM_;
        const float* sb = rope_sin + (size_t)n * ROPE_DIM_;
        float vv[4] = {v.x, v.y, v.z, v.w};
#pragma unroll
        for (int j = 0; j < 4; j++) {
            int rdj = rd + j;
            float partner = (rdj < 32)
                ? -vals[c * HEAD_DIM_ + NOPE_DIM_ + rdj + 32]
                :  vals[c * HEAD_DIM_ + NOPE_DIM_ + rdj - 32];
            vv[j] = vv[j] * cb[rdj] + partner * sb[rdj];
        }
        v.x = vv[0]; v.y = vv[1]; v.z = vv[2]; v.w = vv[3];
    }

    const int slot = slot_mapping[n];
    reinterpret_cast<float4*>(out)[(size_t)slot * 256 + tid] = v;
}

// ---------------------------------------------------------------------------
// host side
// ---------------------------------------------------------------------------
typedef CUresult (*PFN_encodeTiled)(
    CUtensorMap*, CUtensorMapDataType, cuuint32_t, void*,
    const cuuint64_t*, const cuuint64_t*, const cuuint32_t*, const cuuint32_t*,
    CUtensorMapInterleave, CUtensorMapSwizzle, CUtensorMapL2promotion,
    CUtensorMapFloatOOBfill);

static void encode_map_f16(PFN_encodeTiled fn, CUtensorMap* tm, void* p,
                           uint64_t d0, uint64_t d1, uint32_t b0, uint32_t b1) {
    cuuint64_t dims[2]    = {d0, d1};
    cuuint64_t strides[1] = {d0 * 2};
    cuuint32_t box[2]     = {b0, b1};
    cuuint32_t estr[2]    = {1, 1};
    fn(tm, CU_TENSOR_MAP_DATA_TYPE_FLOAT16, 2, p, dims, strides, box, estr,
       CU_TENSOR_MAP_INTERLEAVE_NONE, CU_TENSOR_MAP_SWIZZLE_128B,
       CU_TENSOR_MAP_L2_PROMOTION_L2_128B, CU_TENSOR_MAP_FLOAT_OOB_FILL_NONE);
}

extern "C" void kernel_launch(void* const* d_in, const int* in_sizes, int n_in,
                              void* d_out, int out_size) {
    const float* x     = (const float*)d_in[0];
    const float* wkv   = (const float*)d_in[1];
    const float* wgate = (const float*)d_in[2];
    const float* ape   = (const float*)d_in[3];
    const float* nw    = (const float*)d_in[4];
    const float* rcos  = (const float*)d_in[5];
    const float* rsin  = (const float*)d_in[6];
    const float* cache = (const float*)d_in[7];
    const int*   slots = (const int*)d_in[8];
    float* out = (float*)d_out;

    void* fptr = nullptr;
    cudaDriverEntryPointQueryResult qr;
    cudaGetDriverEntryPointByVersion("cuTensorMapEncodeTiled", &fptr, 12000,
                                     cudaEnableDefault, &qr);
    PFN_encodeTiled enc = (PFN_encodeTiled)fptr;

    void *xh = nullptr, *wkh = nullptr, *wgh = nullptr;
    cudaGetSymbolAddress(&xh,  g_x_h);
    cudaGetSymbolAddress(&wkh, g_wkv_h);
    cudaGetSymbolAddress(&wgh, g_wgate_h);

    CUtensorMap tmx, tmk, tmg;
    encode_map_f16(enc, &tmx, xh,  DIMK, T_TOK, BKE, BM);
    encode_map_f16(enc, &tmk, wkh, DIMK, ED,    BKE, BNH);
    encode_map_f16(enc, &tmg, wgh, DIMK, ED,    BKE, BNH);

    cudaFuncSetAttribute(gemm_tc_kernel,
                         cudaFuncAttributeMaxDynamicSharedMemorySize, SMEM_DYN);

    // memcpy-ONLY side stream (proven zero-alloc); all kernels on stream 0
    static cudaStream_t s_copy = nullptr;
    static cudaEvent_t ev_fork = nullptr, ev_copy = nullptr;
    if (s_copy == nullptr) {
        cudaStreamCreateWithFlags(&s_copy, cudaStreamNonBlocking);
        cudaEventCreateWithFlags(&ev_fork, cudaEventDisableTiming);
        cudaEventCreateWithFlags(&ev_copy, cudaEventDisableTiming);
    }
    cudaEventRecord(ev_fork, 0);
    cudaStreamWaitEvent(s_copy, ev_fork, 0);
    cudaMemcpyAsync(out, cache, (size_t)NUM_SLOTS_ * ED * sizeof(float),
                    cudaMemcpyDeviceToDevice, s_copy);
    cudaEventRecord(ev_copy, s_copy);

    // conversions (default stream): weights (+flag zeroing), then FIRST HALF of x
    cvt_f16_flags_kernel<<<((size_t)ED * DIMK / 4) / 256, 256>>>(wkv, (__half*)wkh);
    cvt_f16_kernel<<<((size_t)ED * DIMK / 4) / 256, 256>>>(wgate, (__half*)wgh);
    cvt_f16_kernel<<<((size_t)(T_TOK / 2) * DIMK / 4) / 256, 256>>>(x, (__half*)xh);

    // persistent GEMM: 64 clusters x 2 jobs; spare warps convert second half of x
    gemm_tc_kernel<<<dim3(128, 1, 1), 256, SMEM_DYN>>>(tmx, tmk, tmg, x, ape);

    cudaStreamWaitEvent(0, ev_copy, 0);
    norm_rope_scatter_kernel<<<NCMP, 256>>>(nw, rcos, rsin, slots, out);
}

// round 17
// speedup vs baseline: 1.1318x; 1.1318x over previous
#include <cuda_runtime.h>
#include <cuda.h>
#include <cuda_fp16.h>
#include <cstdint>

#define T_TOK 8192
#define DIMK 7168
#define ED 1024
#define NCMP 2048
#define HEAD_DIM_ 512
#define ROPE_DIM_ 64
#define NOPE_DIM_ 448
#define NUM_SLOTS_ 65536
#define EPS_ 1e-6f

// persistent cg2 GEMM: 64 clusters x 2 jobs; N=256/pair; split driver threads
#define BM 128
#define BN 256
#define BNH 128
#define BKE 64               // 64 fp16 = 128 B rows
#define NK (DIMK / BKE)                       // 112
#define NJOB 2
#define GTOT (NJOB * NK)                      // 224
#define NSTAGE 4
#define A_OFF 0
#define BP_OFF (BM * BKE * 2)                 // 16384
#define BG_OFF (BP_OFF + BNH * BKE * 2)       // 32768
#define STAGE_BYTES (BG_OFF + BNH * BKE * 2)  // 49152
#define TX_TOTAL (2 * STAGE_BYTES)            // 98304
#define ASUM_OFF (NSTAGE * STAGE_BYTES)       // 196608
#define SMEM_DYN (NSTAGE * STAGE_BYTES + 2048) // 198656

// idesc cg2 kind::f16: dtype=F32(1), N=256, M=256
#define IDESC ((1u << 4) | ((BN / 8) << 17) | ((256 / 16) << 24))

#if defined(__CUDA_ARCH_FEAT_SM103_ALL) || defined(__CUDA_ARCH_FEAT_SM100_ALL) || \
    (defined(__CUDA_ARCH_SPECIFIC__) && (__CUDA_ARCH_SPECIFIC__ >= 1000))
#define HAS_TCGEN05 1
#else
#define HAS_TCGEN05 0
#endif

__device__ float  g_kv_pre[(size_t)NCMP * ED];
__device__ __half g_x_h[(size_t)T_TOK * DIMK];
__device__ __half g_wkv_h[(size_t)ED * DIMK];
__device__ __half g_wgate_h[(size_t)ED * DIMK];

// ---------------------------------------------------------------------------
__device__ __forceinline__ uint32_t smem_u32(const void* p) {
    return (uint32_t)__cvta_generic_to_shared(p);
}
__device__ __forceinline__ uint32_t ctarank() {
    uint32_t r; asm("mov.u32 %0, %%cluster_ctarank;" : "=r"(r)); return r;
}
__device__ __forceinline__ uint64_t make_desc(uint32_t addr) {
    const uint64_t base = (2ull << 61) | (1ull << 46) | (64ull << 32) | (1ull << 16);
    return base | ((uint64_t)(addr >> 4) & 0x3FFF);
}
__device__ __forceinline__ void mbar_init(uint32_t mbar, uint32_t count) {
    asm volatile("mbarrier.init.shared.b64 [%0], %1;" :: "r"(mbar), "r"(count) : "memory");
}
__device__ __forceinline__ void mbar_expect_tx(uint32_t mbar, uint32_t bytes) {
    asm volatile("mbarrier.arrive.expect_tx.shared.b64 _, [%0], %1;"
                 :: "r"(mbar), "r"(bytes) : "memory");
}
__device__ __forceinline__ void mbar_arrive(uint32_t mbar) {
    asm volatile("mbarrier.arrive.shared.b64 _, [%0];" :: "r"(mbar) : "memory");
}
__device__ __forceinline__ void mbar_arrive_cluster(uint32_t local_mbar, uint32_t target_rank) {
    asm volatile(
        "{\n\t.reg .b32 ra;\n\t"
        "mapa.shared::cluster.u32 ra, %0, %1;\n\t"
        "mbarrier.arrive.release.cluster.shared::cluster.b64 _, [ra];\n\t}"
        :: "r"(local_mbar), "r"(target_rank) : "memory");
}
__device__ __forceinline__ void mbar_wait(uint32_t mbar, uint32_t parity) {
    asm volatile(
        "{\n\t.reg .pred P1;\n\t"
        "WAIT_%=:\n\t"
        "mbarrier.try_wait.parity.acquire.cta.shared::cta.b64 P1, [%0], %1, 0x989680;\n\t"
        "@P1 bra DONE_%=;\n\t"
        "bra WAIT_%=;\n\t"
        "DONE_%=:\n\t}"
        :: "r"(mbar), "r"(parity) : "memory");
}
__device__ __forceinline__ void mbar_inval(uint32_t mbar) {
    asm volatile("mbarrier.inval.shared.b64 [%0];" :: "r"(mbar) : "memory");
}
#define CLUSTER_SYNC() do { \
    asm volatile("barrier.cluster.arrive.aligned;" ::: "memory"); \
    asm volatile("barrier.cluster.wait.aligned;" ::: "memory"); \
} while (0)

#if HAS_TCGEN05
__device__ __forceinline__ void tma2d_cg2(uint32_t dst, const CUtensorMap* map,
                                          int cx, int cy, uint32_t mbar) {
    asm volatile(
        "{\n\t.reg .b32 lb;\n\t"
        "and.b32 lb, %4, 0xFEFFFFFF;\n\t"
        "cp.async.bulk.tensor.2d.cta_group::2.shared::cluster.global.tile."
        "mbarrier::complete_tx::bytes [%0], [%1, {%2, %3}], [lb];\n\t}"
        :: "r"(dst), "l"(map), "r"(cx), "r"(cy), "r"(mbar) : "memory");
}
__device__ __forceinline__ void mma_f16_cg2(uint32_t d_tmem, uint64_t a_desc,
                                            uint64_t b_desc, uint32_t idesc, uint32_t en) {
    asm volatile(
        "{\n\t.reg .pred p;\n\t"
        "setp.ne.u32 p, %5, 0;\n\t"
        "tcgen05.mma.cta_group::2.kind::f16 [%0], %1, %2, %3, "
        "{%4, %4, %4, %4, %4, %4, %4, %4}, p;\n\t}"
        :: "r"(d_tmem), "l"(a_desc), "l"(b_desc), "r"(idesc), "r"(0u), "r"(en)
        : "memory");
}
__device__ __forceinline__ void tcg_commit_mc(uint32_t mbar, uint16_t mask) {
    asm volatile(
        "tcgen05.commit.cta_group::2.mbarrier::arrive::one.shared::cluster."
        "multicast::cluster.b64 [%0], %1;"
        :: "r"(mbar), "h"(mask) : "memory");
}
#define TCG_ALLOC_CG2(sm_addr, n) \
    asm volatile("tcgen05.alloc.cta_group::2.sync.aligned.shared::cta.b32 [%0], %1;" \
                 :: "r"(sm_addr), "r"(n) : "memory")
#define TCG_DEALLOC_CG2(tmem, n) \
    asm volatile("tcgen05.dealloc.cta_group::2.sync.aligned.b32 %0, %1;" :: "r"(tmem), "r"(n))
#define TCG_RELINQ_CG2() \
    asm volatile("tcgen05.relinquish_alloc_permit.cta_group::2.sync.aligned;")
#define TCG_FENCE_AFTER()  asm volatile("tcgen05.fence::after_thread_sync;" ::: "memory")
#define TCG_FENCE_BEFORE() asm volatile("tcgen05.fence::before_thread_sync;" ::: "memory")
#define TCG_WAIT_LD()      asm volatile("tcgen05.wait::ld.sync.aligned;" ::: "memory")

#define TCG_LD_X32(r, addr) \
    asm volatile( \
        "tcgen05.ld.sync.aligned.32x32b.x32.b32 " \
        "{%0, %1, %2, %3, %4, %5, %6, %7, " \
        " %8, %9, %10, %11, %12, %13, %14, %15, " \
        " %16, %17, %18, %19, %20, %21, %22, %23, " \
        " %24, %25, %26, %27, %28, %29, %30, %31}, [%32];" \
        : "=r"((r)[0]),  "=r"((r)[1]),  "=r"((r)[2]),  "=r"((r)[3]), \
          "=r"((r)[4]),  "=r"((r)[5]),  "=r"((r)[6]),  "=r"((r)[7]), \
          "=r"((r)[8]),  "=r"((r)[9]),  "=r"((r)[10]), "=r"((r)[11]), \
          "=r"((r)[12]), "=r"((r)[13]), "=r"((r)[14]), "=r"((r)[15]), \
          "=r"((r)[16]), "=r"((r)[17]), "=r"((r)[18]), "=r"((r)[19]), \
          "=r"((r)[20]), "=r"((r)[21]), "=r"((r)[22]), "=r"((r)[23]), \
          "=r"((r)[24]), "=r"((r)[25]), "=r"((r)[26]), "=r"((r)[27]), \
          "=r"((r)[28]), "=r"((r)[29]), "=r"((r)[30]), "=r"((r)[31]) \
        : "r"(addr))
#endif  // HAS_TCGEN05

// ---------------------------------------------------------------------------
__global__ __launch_bounds__(256) void cvt_f16_kernel(
    const float* __restrict__ src, __half* __restrict__ dst)
{
    const size_t i = (size_t)blockIdx.x * 256 + threadIdx.x;
    float4 v = reinterpret_cast<const float4*>(src)[i];
    __half2 lo = __floats2half2_rn(v.x, v.y);
    __half2 hi = __floats2half2_rn(v.z, v.w);
    reinterpret_cast<__half2*>(dst)[2 * i]     = lo;
    reinterpret_cast<__half2*>(dst)[2 * i + 1] = hi;
}

// ---------------------------------------------------------------------------
// persistent cg2 fp16 dual-GEMM: 64 clusters x 2 jobs, split-driver
//   tid 128 (leader): MMA issue only     tid 160 (both CTAs): TMA refill only
//   warps 0-3: epilogue consumers behind done/free barriers
// job mapping: n_tile = cl & 3 (fixed), m_pair_tile = (cl>>2) + 16*j
// ---------------------------------------------------------------------------
__global__ __launch_bounds__(256, 1) __cluster_dims__(2, 1, 1) void gemm_tc_kernel(
    const __grid_constant__ CUtensorMap tmx,
    const __grid_constant__ CUtensorMap tmk,
    const __grid_constant__ CUtensorMap tmg,
    const float* __restrict__ ape)
{
    extern __shared__ float dsm[];
    const int tid  = threadIdx.x;
    const uint32_t rank = ctarank();
    const int cl = blockIdx.x >> 1;            // 0..63
    const int e0 = (cl & 3) * BN;              // N-tile base, fixed

#if HAS_TCGEN05
    const int eb = e0 + (int)rank * BNH;
    __shared__ uint32_t s_tmem;
    __shared__ __align__(8) uint64_t s_mbar[10]; // full[4] empty[4] done free

    const int warp = tid >> 5;
    const int lane = tid & 31;
    const bool leader = (rank == 0);

    const uint32_t sb_raw = smem_u32(dsm);
    const uint32_t base   = (sb_raw + 1023u) & ~1023u;
    float* s_asum = (float*)((char*)dsm + (base - sb_raw) + ASUM_OFF);  // 256 floats
    uint32_t mb_full[NSTAGE], mb_empty[NSTAGE];
#pragma unroll
    for (int s = 0; s < NSTAGE; s++) {
        mb_full[s]  = smem_u32(&s_mbar[s]);
        mb_empty[s] = smem_u32(&s_mbar[NSTAGE + s]);
    }
    const uint32_t mb_done = smem_u32(&s_mbar[8]);
    const uint32_t mb_free = smem_u32(&s_mbar[9]);

    if (warp == 0) TCG_ALLOC_CG2(smem_u32(&s_tmem), 512);
    {
        const int e = e0 + tid;
        s_asum[tid] = ape[e] + ape[ED + e] + ape[2 * ED + e] + ape[3 * ED + e];
    }
    if (tid == 0) {
#pragma unroll
        for (int s = 0; s < NSTAGE; s++) {
            mbar_init(mb_full[s], 1);
            mbar_init(mb_empty[s], 1);
        }
        mbar_init(mb_done, 1);
        mbar_init(mb_free, 8);          // 4 warps x 2 CTAs
        if (leader) {
#pragma unroll
            for (int s = 0; s < NSTAGE; s++) mbar_expect_tx(mb_full[s], TX_TOTAL);
        }
    }
    __syncthreads();
    CLUSTER_SYNC();
    const uint32_t tmem = s_tmem;   // proj @ [0,256), gate @ [256,512)

    if (tid == 160) {
        // ---- refill thread (both CTAs): prefetch + steady-state refills
#pragma unroll
        for (int s = 0; s < NSTAGE; s++) {
            const int ty = (cl >> 2) * 256 + (int)rank * BM;   // job 0
            const uint32_t sa = base + s * STAGE_BYTES;
            tma2d_cg2(sa + A_OFF,  &tmx, s * BKE, ty, mb_full[s]);
            tma2d_cg2(sa + BP_OFF, &tmk, s * BKE, eb, mb_full[s]);
            tma2d_cg2(sa + BG_OFF, &tmg, s * BKE, eb, mb_full[s]);
        }
        int phe[NSTAGE] = {0, 0, 0, 0};
#pragma unroll 1
        for (int t = NSTAGE; t < GTOT; t++) {
            const int s = t & (NSTAGE - 1);
            mbar_wait(mb_empty[s], phe[s]); phe[s] ^= 1;
            const int jt = t / NK;
            const int ck = t - jt * NK;
            const int ty = ((cl >> 2) + 16 * jt) * 256 + (int)rank * BM;
            const uint32_t sa = base + s * STAGE_BYTES;
            tma2d_cg2(sa + A_OFF,  &tmx, ck * BKE, ty, mb_full[s]);
            tma2d_cg2(sa + BP_OFF, &tmk, ck * BKE, eb, mb_full[s]);
            tma2d_cg2(sa + BG_OFF, &tmg, ck * BKE, eb, mb_full[s]);
        }
    } else if (tid == 128 && leader) {
        // ---- MMA driver: minimal per-iteration critical path
        int phf[NSTAGE] = {0, 0, 0, 0};
#pragma unroll 1
        for (int g = 0; g < GTOT; g++) {
            if (g == NK) mbar_wait(mb_free, 0);   // job 1 overwrites TMEM
            const int s = g & (NSTAGE - 1);
            mbar_wait(mb_full[s], phf[s]); phf[s] ^= 1;
            const uint32_t sa = base + s * STAGE_BYTES;
            const uint64_t ad  = make_desc(sa + A_OFF);
            const uint64_t bpd = make_desc(sa + BP_OFF);
            const uint64_t bgd = make_desc(sa + BG_OFF);
            const uint32_t en0 = (g != 0) && (g != NK);
#pragma unroll
            for (int ks = 0; ks < 4; ks++) {
                const uint32_t en = en0 | (uint32_t)(ks > 0);
                mma_f16_cg2(tmem,      ad + 2 * ks, bpd + 2 * ks, IDESC, en);
                mma_f16_cg2(tmem + BN, ad + 2 * ks, bgd + 2 * ks, IDESC, en);
            }
            if (g + NSTAGE < GTOT) mbar_expect_tx(mb_full[s], TX_TOTAL);
            tcg_commit_mc(mb_empty[s], 0x3);
            if (g == NK - 1 || g == GTOT - 1) tcg_commit_mc(mb_done, 0x3);
        }
    } else if (warp < 4) {
        // ---- epilogue consumers
#pragma unroll 1
        for (int j = 0; j < NJOB; j++) {
            mbar_wait(mb_done, j);
            TCG_FENCE_AFTER();
            const int t0j = ((cl >> 2) + 16 * j) * 256 + (int)rank * BM;
            const int n0  = t0j >> 2;
#pragma unroll 1
            for (int cb = 0; cb < 8; cb++) {
                uint32_t pr[32], gr[32];
                TCG_LD_X32(pr, tmem + cb * 32);
                TCG_LD_X32(gr, tmem + BN + cb * 32);
                TCG_WAIT_LD();
                float v[32];
#pragma unroll
                for (int i = 0; i < 32; i++) {
                    float p = __uint_as_float(pr[i]);
                    float gg = __uint_as_float(gr[i]);
                    v[i] = p / (1.f + __expf(-gg));
                }
#pragma unroll
                for (int i = 0; i < 32; i++) {
                    v[i] += __shfl_xor_sync(0xffffffffu, v[i], 1);
                    v[i] += __shfl_xor_sync(0xffffffffu, v[i], 2);
                }
                if ((lane & 3) == 0) {
                    const int row = warp * 8 + (lane >> 2);
                    float* dst = g_kv_pre + (size_t)(n0 + row) * ED + e0 + cb * 32;
                    const float* as = s_asum + cb * 32;
#pragma unroll
                    for (int q = 0; q < 8; q++) {
                        float4 o;
                        o.x = 0.25f * (v[4 * q]     + as[4 * q]);
                        o.y = 0.25f * (v[4 * q + 1] + as[4 * q + 1]);
                        o.z = 0.25f * (v[4 * q + 2] + as[4 * q + 2]);
                        o.w = 0.25f * (v[4 * q + 3] + as[4 * q + 3]);
                        reinterpret_cast<float4*>(dst)[q] = o;
                    }
                }
            }
            TCG_FENCE_BEFORE();
            if (lane == 0) {
                if (leader) mbar_arrive(mb_free);
                else        mbar_arrive_cluster(mb_free, 0);
            }
        }
    }
    __syncthreads();
    CLUSTER_SYNC();   // peer free-arrivals land before inval
    if (tid == 0) {
#pragma unroll
        for (int s = 0; s < NSTAGE; s++) { mbar_inval(mb_full[s]); mbar_inval(mb_empty[s]); }
        mbar_inval(mb_done);
        mbar_inval(mb_free);
    }
    __syncthreads();
    if (warp == 0) { TCG_RELINQ_CG2(); TCG_DEALLOC_CG2(tmem, 512); }
    CLUSTER_SYNC();

#else  // ---- generic-PTX fallback (correct, never executed on GB300) ----
    for (int j = 0; j < NJOB; j++) {
        const int t0j = ((cl >> 2) + 16 * j) * 256 + (int)rank * BM;
        const int n0 = t0j >> 2;
        for (int idx = tid; idx < 32 * BN; idx += 256) {
            int row = idx / BN, col = idx % BN;
            int e = e0 + col;
            float acc = 0.f;
            for (int r = 0; r < 4; r++) {
                const __half* xr = g_x_h + (size_t)(t0j + row * 4 + r) * DIMK;
                const __half* wk = g_wkv_h + (size_t)e * DIMK;
                const __half* wg = g_wgate_h + (size_t)e * DIMK;
                float p = 0.f, g = 0.f;
                for (int k = 0; k < DIMK; k++) {
                    p += __half2float(xr[k]) * __half2float(wk[k]);
                    g += __half2float(xr[k]) * __half2float(wg[k]);
                }
                acc += p / (1.f + __expf(-g));
            }
            float asum = ape[e] + ape[ED + e] + ape[2 * ED + e] + ape[3 * ED + e];
            g_kv_pre[(size_t)(n0 + row) * ED + e] = 0.25f * (acc + asum);
        }
    }
    (void)dsm;
#endif
}

// ---------------------------------------------------------------------------
// RMS-norm (per 512) + partial RoPE + scatter
// ---------------------------------------------------------------------------
__global__ __launch_bounds__(256) void norm_rope_scatter_kernel(
    const float* __restrict__ norm_weight, const float* __restrict__ rope_cos,
    const float* __restrict__ rope_sin, const int* __restrict__ slot_mapping,
    float* __restrict__ out)
{
    __shared__ float vals[ED];
    __shared__ float wsum[8];
    const int n = blockIdx.x;
    const int tid = threadIdx.x;

    float4 v = reinterpret_cast<const float4*>(g_kv_pre)[(size_t)n * 256 + tid];
    float ssq = v.x * v.x + v.y * v.y + v.z * v.z + v.w * v.w;
#pragma unroll
    for (int off = 16; off > 0; off >>= 1)
        ssq += __shfl_xor_sync(0xffffffffu, ssq, off);
    if ((tid & 31) == 0) wsum[tid >> 5] = ssq;
    __syncthreads();

    const int c = tid >> 7;
    float tot = wsum[c * 4] + wsum[c * 4 + 1] + wsum[c * 4 + 2] + wsum[c * 4 + 3];
    float scale = rsqrtf(tot * (1.0f / HEAD_DIM_) + EPS_);
    float4 nw = reinterpret_cast<const float4*>(norm_weight)[tid & 127];
    v.x *= scale * nw.x; v.y *= scale * nw.y; v.z *= scale * nw.z; v.w *= scale * nw.w;
    reinterpret_cast<float4*>(vals)[tid] = v;
    __syncthreads();

    const int din = tid & 127;
    if (din >= 112) {
        int rd = (din - 112) * 4;
        const float* cb = rope_cos + (size_t)n * ROPE_DIM_;
        const float* sb = rope_sin + (size_t)n * ROPE_DIM_;
        float vv[4] = {v.x, v.y, v.z, v.w};
#pragma unroll
        for (int j = 0; j < 4; j++) {
            int rdj = rd + j;
            float partner = (rdj < 32)
                ? -vals[c * HEAD_DIM_ + NOPE_DIM_ + rdj + 32]
                :  vals[c * HEAD_DIM_ + NOPE_DIM_ + rdj - 32];
            vv[j] = vv[j] * cb[rdj] + partner * sb[rdj];
        }
        v.x = vv[0]; v.y = vv[1]; v.z = vv[2]; v.w = vv[3];
    }

    const int slot = slot_mapping[n];
    reinterpret_cast<float4*>(out)[(size_t)slot * 256 + tid] = v;
}

// ---------------------------------------------------------------------------
// host side
// ---------------------------------------------------------------------------
typedef CUresult (*PFN_encodeTiled)(
    CUtensorMap*, CUtensorMapDataType, cuuint32_t, void*,
    const cuuint64_t*, const cuuint64_t*, const cuuint32_t*, const cuuint32_t*,
    CUtensorMapInterleave, CUtensorMapSwizzle, CUtensorMapL2promotion,
    CUtensorMapFloatOOBfill);

static void encode_map_f16(PFN_encodeTiled fn, CUtensorMap* tm, void* p,
                           uint64_t d0, uint64_t d1, uint32_t b0, uint32_t b1) {
    cuuint64_t dims[2]    = {d0, d1};
    cuuint64_t strides[1] = {d0 * 2};
    cuuint32_t box[2]     = {b0, b1};
    cuuint32_t estr[2]    = {1, 1};
    fn(tm, CU_TENSOR_MAP_DATA_TYPE_FLOAT16, 2, p, dims, strides, box, estr,
       CU_TENSOR_MAP_INTERLEAVE_NONE, CU_TENSOR_MAP_SWIZZLE_128B,
       CU_TENSOR_MAP_L2_PROMOTION_L2_128B, CU_TENSOR_MAP_FLOAT_OOB_FILL_NONE);
}

extern "C" void kernel_launch(void* const* d_in, const int* in_sizes, int n_in,
                              void* d_out, int out_size) {
    const float* x     = (const float*)d_in[0];
    const float* wkv   = (const float*)d_in[1];
    const float* wgate = (const float*)d_in[2];
    const float* ape   = (const float*)d_in[3];
    const float* nw    = (const float*)d_in[4];
    const float* rcos  = (const float*)d_in[5];
    const float* rsin  = (const float*)d_in[6];
    const float* cache = (const float*)d_in[7];
    const int*   slots = (const int*)d_in[8];
    float* out = (float*)d_out;

    void* fptr = nullptr;
    cudaDriverEntryPointQueryResult qr;
    cudaGetDriverEntryPointByVersion("cuTensorMapEncodeTiled", &fptr, 12000,
                                     cudaEnableDefault, &qr);
    PFN_encodeTiled enc = (PFN_encodeTiled)fptr;

    void *xh = nullptr, *wkh = nullptr, *wgh = nullptr;
    cudaGetSymbolAddress(&xh,  g_x_h);
    cudaGetSymbolAddress(&wkh, g_wkv_h);
    cudaGetSymbolAddress(&wgh, g_wgate_h);

    CUtensorMap tmx, tmk, tmg;
    encode_map_f16(enc, &tmx, xh,  DIMK, T_TOK, BKE, BM);
    encode_map_f16(enc, &tmk, wkh, DIMK, ED,    BKE, BNH);
    encode_map_f16(enc, &tmg, wgh, DIMK, ED,    BKE, BNH);

    cudaFuncSetAttribute(gemm_tc_kernel,
                         cudaFuncAttributeMaxDynamicSharedMemorySize, SMEM_DYN);

    // memcpy-ONLY side stream (proven zero-alloc); all kernels on stream 0
    static cudaStream_t s_copy = nullptr;
    static cudaEvent_t ev_fork = nullptr, ev_copy = nullptr;
    if (s_copy == nullptr) {
        cudaStreamCreateWithFlags(&s_copy, cudaStreamNonBlocking);
        cudaEventCreateWithFlags(&ev_fork, cudaEventDisableTiming);
        cudaEventCreateWithFlags(&ev_copy, cudaEventDisableTiming);
    }

    // conversions first, at full DRAM bandwidth (no copy contention)
    cvt_f16_kernel<<<((size_t)ED * DIMK / 4) / 256, 256>>>(wkv,   (__half*)wkh);
    cvt_f16_kernel<<<((size_t)ED * DIMK / 4) / 256, 256>>>(wgate, (__half*)wgh);
    cvt_f16_kernel<<<((size_t)T_TOK * DIMK / 4) / 256, 256>>>(x,  (__half*)xh);

    // fork the 512MB cache copy to overlap the (DRAM-light) GEMM window
    cudaEventRecord(ev_fork, 0);
    cudaStreamWaitEvent(s_copy, ev_fork, 0);
    cudaMemcpyAsync(out, cache, (size_t)NUM_SLOTS_ * ED * sizeof(float),
                    cudaMemcpyDeviceToDevice, s_copy);
    cudaEventRecord(ev_copy, s_copy);

    // persistent GEMM: 64 clusters x 2 jobs = 128 CTAs, single wave
    gemm_tc_kernel<<<dim3(128, 1, 1), 256, SMEM_DYN>>>(tmx, tmk, tmg, ape);

    cudaStreamWaitEvent(0, ev_copy, 0);
    norm_rope_scatter_kernel<<<NCMP, 256>>>(nw, rcos, rsin, slots, out);
}